// round 14
// baseline (speedup 1.0000x reference)
#include <cuda_runtime.h>

#define Ld 4096
#define Hd 512
#define Md 1024
#define G4H 2048
#define NCTA 128

// ---------------- scratch (device globals; no allocations allowed) ------------
__device__ float g_x0[Ld * Hd];          // x after embed; later x+att@A in place
__device__ float g_scores[Ld * Md];      // raw scores (softmax fused into gemm_nn)
__device__ float g_pre[Ld * G4H];        // x @ W_ih^T + b_ih + b_hh
__device__ float g_pmax[128 * Md];
__device__ float g_psum[128 * Md];
__device__ float g_colmax[Md];
__device__ float g_colsumr[Md];
__device__ unsigned long long g_hpair[2][Hd];   // {tag(hi32), value bits(lo32)}

// ---------------- helpers ------------------------------------------------------
__device__ __forceinline__ unsigned long long ld_acq_u64(const unsigned long long* p) {
    unsigned long long v;
    asm volatile("ld.acquire.gpu.global.b64 %0, [%1];" : "=l"(v) : "l"(p) : "memory");
    return v;
}
__device__ __forceinline__ void st_rel_u64(unsigned long long* p, unsigned long long v) {
    asm volatile("st.release.gpu.global.b64 [%0], %1;" :: "l"(p), "l"(v) : "memory");
}
__device__ __forceinline__ void sleep_ns(unsigned ns) {
    asm volatile("nanosleep.u32 %0;" :: "r"(ns));
}
__device__ __forceinline__ float sigf(float x) { return 1.0f / (1.0f + __expf(-x)); }
// exact-identity tanh via __expf (same error class as sigf; avoids branchy tanhf)
__device__ __forceinline__ float tanh_acc(float x) {
    return fmaf(2.0f, 1.0f / (1.0f + __expf(-2.0f * x)), -1.0f);
}

// ---------------- init ---------------------------------------------------------
__global__ void init_pairs_kernel() {
    int i = blockIdx.x * blockDim.x + threadIdx.x;   // 2*Hd entries
    if (i < 2 * Hd) ((unsigned long long*)g_hpair)[i] = 0ull;
}

// ---------------- embedding gather ---------------------------------------------
__global__ __launch_bounds__(128) void embed_kernel(const int* __restrict__ sent,
                                                    const float* __restrict__ embed) {
    int l = blockIdx.x;
    int idx = sent[l];
    const float4* src = (const float4*)(embed + (size_t)idx * Hd);
    float4* dst = (float4*)(g_x0 + (size_t)l * Hd);
    dst[threadIdx.x] = src[threadIdx.x];
}

// ---------------- tiled SGEMM (NT): C[M,N] = A[M,K] * B[N,K]^T (+bias1+bias2) ---
#define BM 128
#define BN 128
#define BK 16
__global__ __launch_bounds__(256) void gemm_nt_kernel(
    float* __restrict__ C, const float* __restrict__ A, const float* __restrict__ B,
    int M, int N, int K, const float* __restrict__ bias1, const float* __restrict__ bias2)
{
    __shared__ float As[BK][BM + 4];
    __shared__ float Bs[BK][BN + 4];
    int tid = threadIdx.x;
    int bm = blockIdx.y * BM, bn = blockIdx.x * BN;
    int tx = tid & 15, ty = tid >> 4;
    float acc[8][8] = {};
    for (int kk = 0; kk < K; kk += BK) {
#pragma unroll
        for (int i = 0; i < 2; i++) {
            int idx = tid + i * 256;
            int row = idx >> 2, kc = (idx & 3) << 2;
            float4 v = *(const float4*)(A + (size_t)(bm + row) * K + kk + kc);
            As[kc + 0][row] = v.x; As[kc + 1][row] = v.y;
            As[kc + 2][row] = v.z; As[kc + 3][row] = v.w;
        }
#pragma unroll
        for (int i = 0; i < 2; i++) {
            int idx = tid + i * 256;
            int row = idx >> 2, kc = (idx & 3) << 2;
            float4 v = *(const float4*)(B + (size_t)(bn + row) * K + kk + kc);
            Bs[kc + 0][row] = v.x; Bs[kc + 1][row] = v.y;
            Bs[kc + 2][row] = v.z; Bs[kc + 3][row] = v.w;
        }
        __syncthreads();
#pragma unroll
        for (int k = 0; k < BK; k++) {
            float ar[8], br[8];
            *(float4*)(ar)     = *(const float4*)&As[k][ty * 8];
            *(float4*)(ar + 4) = *(const float4*)&As[k][ty * 8 + 4];
            *(float4*)(br)     = *(const float4*)&Bs[k][tx * 8];
            *(float4*)(br + 4) = *(const float4*)&Bs[k][tx * 8 + 4];
#pragma unroll
            for (int i = 0; i < 8; i++)
#pragma unroll
                for (int j = 0; j < 8; j++)
                    acc[i][j] = fmaf(ar[i], br[j], acc[i][j]);
        }
        __syncthreads();
    }
    float bb[8];
#pragma unroll
    for (int j = 0; j < 8; j++) {
        float b = 0.f;
        if (bias1) b += bias1[bn + tx * 8 + j];
        if (bias2) b += bias2[bn + tx * 8 + j];
        bb[j] = b;
    }
#pragma unroll
    for (int i = 0; i < 8; i++) {
        float* cp = C + (size_t)(bm + ty * 8 + i) * N + bn + tx * 8;
#pragma unroll
        for (int j = 0; j < 8; j++) cp[j] = acc[i][j] + bb[j];
    }
}

// ---------------- tiled SGEMM (NN) with fused softmax on A ----------------------
// C[M,N] = softmaxA[M,K] * B[K,N] + addend, where
// softmaxA[l,k] = exp(A[l,k]-colmax[k]) * colsumr[k]
__global__ __launch_bounds__(256) void gemm_nn_smax_kernel(
    float* __restrict__ C, const float* __restrict__ A, const float* __restrict__ B,
    int M, int N, int K, const float* __restrict__ addend)
{
    __shared__ float As[BK][BM + 4];
    __shared__ float Bs[BK][BN + 4];
    int tid = threadIdx.x;
    int bm = blockIdx.y * BM, bn = blockIdx.x * BN;
    int tx = tid & 15, ty = tid >> 4;
    float acc[8][8] = {};
    for (int kk = 0; kk < K; kk += BK) {
#pragma unroll
        for (int i = 0; i < 2; i++) {
            int idx = tid + i * 256;
            int row = idx >> 2, kc = (idx & 3) << 2;
            float4 v = *(const float4*)(A + (size_t)(bm + row) * K + kk + kc);
            float4 cm = *(const float4*)&g_colmax[kk + kc];
            float4 cr = *(const float4*)&g_colsumr[kk + kc];
            As[kc + 0][row] = __expf(v.x - cm.x) * cr.x;
            As[kc + 1][row] = __expf(v.y - cm.y) * cr.y;
            As[kc + 2][row] = __expf(v.z - cm.z) * cr.z;
            As[kc + 3][row] = __expf(v.w - cm.w) * cr.w;
        }
#pragma unroll
        for (int i = 0; i < 2; i++) {
            int idx = tid + i * 256;
            int kr = idx >> 5, col = (idx & 31) << 2;
            float4 v = *(const float4*)(B + (size_t)(kk + kr) * N + bn + col);
            *(float4*)&Bs[kr][col] = v;
        }
        __syncthreads();
#pragma unroll
        for (int k = 0; k < BK; k++) {
            float ar[8], br[8];
            *(float4*)(ar)     = *(const float4*)&As[k][ty * 8];
            *(float4*)(ar + 4) = *(const float4*)&As[k][ty * 8 + 4];
            *(float4*)(br)     = *(const float4*)&Bs[k][tx * 8];
            *(float4*)(br + 4) = *(const float4*)&Bs[k][tx * 8 + 4];
#pragma unroll
            for (int i = 0; i < 8; i++)
#pragma unroll
                for (int j = 0; j < 8; j++)
                    acc[i][j] = fmaf(ar[i], br[j], acc[i][j]);
        }
        __syncthreads();
    }
#pragma unroll
    for (int i = 0; i < 8; i++) {
        size_t off = (size_t)(bm + ty * 8 + i) * N + bn + tx * 8;
        float* cp = C + off;
        const float* ap = addend + off;
#pragma unroll
        for (int j = 0; j < 8; j++) cp[j] = acc[i][j] + ap[j];
    }
}

// ---------------- column softmax stats (over L) — deterministic two-level -------
__global__ __launch_bounds__(256) void smax_pmax_kernel() {
    int cb = blockIdx.x;
    float m[4] = {-3.4e38f, -3.4e38f, -3.4e38f, -3.4e38f};
    for (int r = 0; r < 32; r++) {
        const float* row = g_scores + (size_t)(cb * 32 + r) * Md;
#pragma unroll
        for (int j = 0; j < 4; j++)
            m[j] = fmaxf(m[j], row[threadIdx.x + j * 256]);
    }
#pragma unroll
    for (int j = 0; j < 4; j++)
        g_pmax[(size_t)cb * Md + threadIdx.x + j * 256] = m[j];
}
__global__ __launch_bounds__(256) void smax_cmax_kernel() {
    int c = blockIdx.x * 256 + threadIdx.x;
    float m = -3.4e38f;
    for (int b = 0; b < 128; b++) m = fmaxf(m, g_pmax[(size_t)b * Md + c]);
    g_colmax[c] = m;
}
__global__ __launch_bounds__(256) void smax_psum_kernel() {
    int cb = blockIdx.x;
    float cm[4], s[4] = {0.f, 0.f, 0.f, 0.f};
#pragma unroll
    for (int j = 0; j < 4; j++) cm[j] = g_colmax[threadIdx.x + j * 256];
    for (int r = 0; r < 32; r++) {
        const float* row = g_scores + (size_t)(cb * 32 + r) * Md;
#pragma unroll
        for (int j = 0; j < 4; j++)
            s[j] += __expf(row[threadIdx.x + j * 256] - cm[j]);
    }
#pragma unroll
    for (int j = 0; j < 4; j++)
        g_psum[(size_t)cb * Md + threadIdx.x + j * 256] = s[j];
}
__global__ __launch_bounds__(256) void smax_csum_kernel() {
    int c = blockIdx.x * 256 + threadIdx.x;
    float s = 0.f;
    for (int b = 0; b < 128; b++) s += g_psum[(size_t)b * Md + c];
    g_colsumr[c] = 1.0f / s;
}

// ---------------- A -> A_new[0:1024] copy ---------------------------------------
__global__ __launch_bounds__(256) void copyA_kernel(const float* __restrict__ A,
                                                    float* __restrict__ dst) {
    size_t i = (size_t)blockIdx.x * blockDim.x + threadIdx.x;   // float4 index
    ((float4*)dst)[i] = ((const float4*)A)[i];
}

// ---------------- persistent LSTM scan ------------------------------------------
// 128 CTAs x 256 threads. CTA b owns h indices [4b, 4b+4) -> 16 gate rows.
// Warp w computes gate rows 2w, 2w+1. Lane l owns h-slice [16l, 16l+16).
// Exchange: self-validating {value, step-tag} u64 words, strong release/acquire
// (champion structure). NEW: poll BACKOFF — after 2 failed rounds each poller
// nanosleeps 40ns between retries, draining the L2/LSU spin storm so the
// producers' release stores are not queued behind spinning readers.
__global__ __launch_bounds__(256, 1) void lstm_kernel(
    const float* __restrict__ Whh, const float* __restrict__ h0,
    const float* __restrict__ c0, float* __restrict__ out_h,
    float* __restrict__ out_c, float* __restrict__ out_seq,
    float* __restrict__ out_anew_last)
{
    __shared__ float hs[Hd];
    __shared__ float gs[16];
    int bid = blockIdx.x, tid = threadIdx.x;
    int w = tid >> 5, l = tid & 31;
    int rl0 = 2 * w, rl1 = 2 * w + 1;
    // global gate row: gate g = r>>2 (i,f,g,o blocks of 512), within-gate idx bid*4+(r&3)
    int grow0 = (rl0 >> 2) * Hd + bid * 4 + (rl0 & 3);
    int grow1 = (rl1 >> 2) * Hd + bid * 4 + (rl1 & 3);   // == grow0 + 1

    float wr0[16], wr1[16];
    {
        const float4* p0 = (const float4*)(Whh + (size_t)grow0 * Hd + l * 16);
        const float4* p1 = (const float4*)(Whh + (size_t)grow1 * Hd + l * 16);
#pragma unroll
        for (int m = 0; m < 4; m++) {
            float4 v0 = p0[m], v1 = p1[m];
            wr0[4 * m + 0] = v0.x; wr0[4 * m + 1] = v0.y;
            wr0[4 * m + 2] = v0.z; wr0[4 * m + 3] = v0.w;
            wr1[4 * m + 0] = v1.x; wr1[4 * m + 1] = v1.y;
            wr1[4 * m + 2] = v1.z; wr1[4 * m + 3] = v1.w;
        }
    }
    hs[tid] = h0[tid];
    hs[tid + 256] = h0[tid + 256];
    float creg = (tid < 4) ? c0[bid * 4 + tid] : 0.f;
    __syncthreads();

    for (int t = 0; t < Ld; t++) {
        // overlap: lane0 of each warp prefetches the two pre-activations (adjacent)
        float2 pre2 = make_float2(0.f, 0.f);
        if (l == 0)
            pre2 = __ldcg((const float2*)&g_pre[(size_t)t * G4H + grow0]);

        // dot products over the owned 16-slice (LDS.128, conflict-free)
        float a0 = 0.f, a1 = 0.f;
#pragma unroll
        for (int m = 0; m < 4; m++) {
            float4 h4 = *(const float4*)&hs[l * 16 + 4 * m];
            a0 = fmaf(wr0[4 * m + 0], h4.x, a0); a1 = fmaf(wr1[4 * m + 0], h4.x, a1);
            a0 = fmaf(wr0[4 * m + 1], h4.y, a0); a1 = fmaf(wr1[4 * m + 1], h4.y, a1);
            a0 = fmaf(wr0[4 * m + 2], h4.z, a0); a1 = fmaf(wr1[4 * m + 2], h4.z, a1);
            a0 = fmaf(wr0[4 * m + 3], h4.w, a0); a1 = fmaf(wr1[4 * m + 3], h4.w, a1);
        }
#pragma unroll
        for (int off = 16; off > 0; off >>= 1) {
            a0 += __shfl_down_sync(0xffffffffu, a0, off);
            a1 += __shfl_down_sync(0xffffffffu, a1, off);
        }
        if (l == 0) { gs[rl0] = a0 + pre2.x; gs[rl1] = a1 + pre2.y; }
        __syncthreads();

        int nb = (t + 1) & 1;
        unsigned tgt = (unsigned)(t + 1);

        if (tid < 4) {
            float iv = sigf(gs[tid]);
            float fv = sigf(gs[4 + tid]);
            float gv = tanh_acc(gs[8 + tid]);
            float ov = sigf(gs[12 + tid]);
            float cv = fmaf(fv, creg, iv * gv);
            creg = cv;
            float hv = ov * tanh_acc(cv);
            int hidx = bid * 4 + tid;
            unsigned long long pkt =
                ((unsigned long long)tgt << 32) | (unsigned long long)__float_as_uint(hv);
            st_rel_u64(&g_hpair[nb][hidx], pkt);          // strong release publish
            __stcg(&out_seq[(size_t)t * Hd + hidx], hv);
            if (t == Ld - 1) {
                out_h[hidx] = hv;
                out_c[hidx] = cv;
                out_anew_last[hidx] = hv;
            }
        }
        if (t == Ld - 1) break;

        // poll BOTH tagged words concurrently; nanosleep backoff after 2 misses
        {
            const unsigned long long* p0 = &g_hpair[nb][tid];
            const unsigned long long* p1 = &g_hpair[nb][tid + 256];
            unsigned long long v0 = ld_acq_u64(p0);
            unsigned long long v1 = ld_acq_u64(p1);
            bool ok0 = (unsigned)(v0 >> 32) >= tgt;
            bool ok1 = (unsigned)(v1 >> 32) >= tgt;
            int spins = 0;
            while (!(ok0 && ok1)) {
                if (++spins > 2) sleep_ns(40u);
                if (!ok0) { v0 = ld_acq_u64(p0); ok0 = (unsigned)(v0 >> 32) >= tgt; }
                if (!ok1) { v1 = ld_acq_u64(p1); ok1 = (unsigned)(v1 >> 32) >= tgt; }
            }
            hs[tid]       = __uint_as_float((unsigned)v0);
            hs[tid + 256] = __uint_as_float((unsigned)v1);
        }
        __syncthreads();
    }
}

// ---------------- launch ---------------------------------------------------------
extern "C" void kernel_launch(void* const* d_in, const int* in_sizes, int n_in,
                              void* d_out, int out_size) {
    const int*   sent  = (const int*)d_in[0];
    const float* h0    = (const float*)d_in[1];
    const float* c0    = (const float*)d_in[2];
    const float* A     = (const float*)d_in[3];
    const float* embed = (const float*)d_in[4];
    const float* W_ih  = (const float*)d_in[5];
    const float* W_hh  = (const float*)d_in[6];
    const float* b_ih  = (const float*)d_in[7];
    const float* b_hh  = (const float*)d_in[8];

    float* out = (float*)d_out;
    float* out_h = out;
    float* out_c = out + Hd;
    float* out_seq = out + 2 * Hd;
    float* out_anew = out + 2 * Hd + (size_t)Ld * Hd;
    float* out_anew_last = out_anew + (size_t)Md * Hd;

    float* d_x0; float* d_scores; float* d_pre;
    cudaGetSymbolAddress((void**)&d_x0, g_x0);
    cudaGetSymbolAddress((void**)&d_scores, g_scores);
    cudaGetSymbolAddress((void**)&d_pre, g_pre);

    init_pairs_kernel<<<4, 256>>>();
    embed_kernel<<<Ld, 128>>>(sent, embed);

    // scores = x0 @ A^T   [4096,1024]
    gemm_nt_kernel<<<dim3(Md / BN, Ld / BM), 256>>>(d_scores, d_x0, A,
                                                    Ld, Md, Hd, nullptr, nullptr);
    // softmax stats over L (columns) — normalization fused into next GEMM
    smax_pmax_kernel<<<128, 256>>>();
    smax_cmax_kernel<<<Md / 256, 256>>>();
    smax_psum_kernel<<<128, 256>>>();
    smax_csum_kernel<<<Md / 256, 256>>>();

    // x = x0 + softmax(scores) @ A    [4096,512] (in place into g_x0)
    gemm_nn_smax_kernel<<<dim3(Hd / BN, Ld / BM), 256>>>(d_x0, d_scores, A,
                                                         Ld, Hd, Md, d_x0);
    // pre = x @ W_ih^T + b_ih + b_hh   [4096,2048]
    gemm_nt_kernel<<<dim3(G4H / BN, Ld / BM), 256>>>(d_pre, d_x0, W_ih,
                                                     Ld, G4H, Hd, b_ih, b_hh);
    // A_new rows 0..1023
    copyA_kernel<<<(Md * Hd / 4) / 256, 256>>>(A, out_anew);

    // LSTM scan (persistent, 128 CTAs)
    lstm_kernel<<<NCTA, 256>>>(W_hh, h0, c0, out_h, out_c, out_seq, out_anew_last);
}

// round 15
// speedup vs baseline: 1.3356x; 1.3356x over previous
#include <cuda_runtime.h>

#define Ld 4096
#define Hd 512
#define Md 1024
#define G4H 2048
#define NCTA 128

// ---------------- scratch (device globals; no allocations allowed) ------------
__device__ float g_x0[Ld * Hd];          // x after embed; later x+att@A in place
__device__ float g_scores[Ld * Md];      // raw scores (softmax fused into gemm_nn)
__device__ float g_pre[Ld * G4H];        // x @ W_ih^T + b_ih + b_hh
__device__ float g_pmax[128 * Md];
__device__ float g_psum[128 * Md];
__device__ float g_colmax[Md];
__device__ float g_colsumr[Md];
__device__ unsigned long long g_hpair[2][Hd];   // {tag(hi32), value bits(lo32)}

// ---------------- helpers ------------------------------------------------------
// RELAXED strong ops: single-copy atomic (all we need for self-validating
// {tag,value} words) WITHOUT release/acquire ordering. The release publish was
// waiting on the prior step's DRAM-bound out_seq store every iteration.
__device__ __forceinline__ unsigned long long ld_rlx_u64(const unsigned long long* p) {
    unsigned long long v;
    asm volatile("ld.relaxed.gpu.global.b64 %0, [%1];" : "=l"(v) : "l"(p) : "memory");
    return v;
}
__device__ __forceinline__ void st_rlx_u64(unsigned long long* p, unsigned long long v) {
    asm volatile("st.relaxed.gpu.global.b64 [%0], %1;" :: "l"(p), "l"(v) : "memory");
}
__device__ __forceinline__ float sigf(float x) { return 1.0f / (1.0f + __expf(-x)); }
// exact-identity tanh via __expf (same error class as sigf; avoids branchy tanhf)
__device__ __forceinline__ float tanh_acc(float x) {
    return fmaf(2.0f, 1.0f / (1.0f + __expf(-2.0f * x)), -1.0f);
}

// ---------------- init ---------------------------------------------------------
__global__ void init_pairs_kernel() {
    int i = blockIdx.x * blockDim.x + threadIdx.x;   // 2*Hd entries
    if (i < 2 * Hd) ((unsigned long long*)g_hpair)[i] = 0ull;
}

// ---------------- embedding gather ---------------------------------------------
__global__ __launch_bounds__(128) void embed_kernel(const int* __restrict__ sent,
                                                    const float* __restrict__ embed) {
    int l = blockIdx.x;
    int idx = sent[l];
    const float4* src = (const float4*)(embed + (size_t)idx * Hd);
    float4* dst = (float4*)(g_x0 + (size_t)l * Hd);
    dst[threadIdx.x] = src[threadIdx.x];
}

// ---------------- tiled SGEMM (NT): C[M,N] = A[M,K] * B[N,K]^T (+bias1+bias2) ---
#define BM 128
#define BN 128
#define BK 16
__global__ __launch_bounds__(256) void gemm_nt_kernel(
    float* __restrict__ C, const float* __restrict__ A, const float* __restrict__ B,
    int M, int N, int K, const float* __restrict__ bias1, const float* __restrict__ bias2)
{
    __shared__ float As[BK][BM + 4];
    __shared__ float Bs[BK][BN + 4];
    int tid = threadIdx.x;
    int bm = blockIdx.y * BM, bn = blockIdx.x * BN;
    int tx = tid & 15, ty = tid >> 4;
    float acc[8][8] = {};
    for (int kk = 0; kk < K; kk += BK) {
#pragma unroll
        for (int i = 0; i < 2; i++) {
            int idx = tid + i * 256;
            int row = idx >> 2, kc = (idx & 3) << 2;
            float4 v = *(const float4*)(A + (size_t)(bm + row) * K + kk + kc);
            As[kc + 0][row] = v.x; As[kc + 1][row] = v.y;
            As[kc + 2][row] = v.z; As[kc + 3][row] = v.w;
        }
#pragma unroll
        for (int i = 0; i < 2; i++) {
            int idx = tid + i * 256;
            int row = idx >> 2, kc = (idx & 3) << 2;
            float4 v = *(const float4*)(B + (size_t)(bn + row) * K + kk + kc);
            Bs[kc + 0][row] = v.x; Bs[kc + 1][row] = v.y;
            Bs[kc + 2][row] = v.z; Bs[kc + 3][row] = v.w;
        }
        __syncthreads();
#pragma unroll
        for (int k = 0; k < BK; k++) {
            float ar[8], br[8];
            *(float4*)(ar)     = *(const float4*)&As[k][ty * 8];
            *(float4*)(ar + 4) = *(const float4*)&As[k][ty * 8 + 4];
            *(float4*)(br)     = *(const float4*)&Bs[k][tx * 8];
            *(float4*)(br + 4) = *(const float4*)&Bs[k][tx * 8 + 4];
#pragma unroll
            for (int i = 0; i < 8; i++)
#pragma unroll
                for (int j = 0; j < 8; j++)
                    acc[i][j] = fmaf(ar[i], br[j], acc[i][j]);
        }
        __syncthreads();
    }
    float bb[8];
#pragma unroll
    for (int j = 0; j < 8; j++) {
        float b = 0.f;
        if (bias1) b += bias1[bn + tx * 8 + j];
        if (bias2) b += bias2[bn + tx * 8 + j];
        bb[j] = b;
    }
#pragma unroll
    for (int i = 0; i < 8; i++) {
        float* cp = C + (size_t)(bm + ty * 8 + i) * N + bn + tx * 8;
#pragma unroll
        for (int j = 0; j < 8; j++) cp[j] = acc[i][j] + bb[j];
    }
}

// ---------------- tiled SGEMM (NN) with fused softmax on A ----------------------
__global__ __launch_bounds__(256) void gemm_nn_smax_kernel(
    float* __restrict__ C, const float* __restrict__ A, const float* __restrict__ B,
    int M, int N, int K, const float* __restrict__ addend)
{
    __shared__ float As[BK][BM + 4];
    __shared__ float Bs[BK][BN + 4];
    int tid = threadIdx.x;
    int bm = blockIdx.y * BM, bn = blockIdx.x * BN;
    int tx = tid & 15, ty = tid >> 4;
    float acc[8][8] = {};
    for (int kk = 0; kk < K; kk += BK) {
#pragma unroll
        for (int i = 0; i < 2; i++) {
            int idx = tid + i * 256;
            int row = idx >> 2, kc = (idx & 3) << 2;
            float4 v = *(const float4*)(A + (size_t)(bm + row) * K + kk + kc);
            float4 cm = *(const float4*)&g_colmax[kk + kc];
            float4 cr = *(const float4*)&g_colsumr[kk + kc];
            As[kc + 0][row] = __expf(v.x - cm.x) * cr.x;
            As[kc + 1][row] = __expf(v.y - cm.y) * cr.y;
            As[kc + 2][row] = __expf(v.z - cm.z) * cr.z;
            As[kc + 3][row] = __expf(v.w - cm.w) * cr.w;
        }
#pragma unroll
        for (int i = 0; i < 2; i++) {
            int idx = tid + i * 256;
            int kr = idx >> 5, col = (idx & 31) << 2;
            float4 v = *(const float4*)(B + (size_t)(kk + kr) * N + bn + col);
            *(float4*)&Bs[kr][col] = v;
        }
        __syncthreads();
#pragma unroll
        for (int k = 0; k < BK; k++) {
            float ar[8], br[8];
            *(float4*)(ar)     = *(const float4*)&As[k][ty * 8];
            *(float4*)(ar + 4) = *(const float4*)&As[k][ty * 8 + 4];
            *(float4*)(br)     = *(const float4*)&Bs[k][tx * 8];
            *(float4*)(br + 4) = *(const float4*)&Bs[k][tx * 8 + 4];
#pragma unroll
            for (int i = 0; i < 8; i++)
#pragma unroll
                for (int j = 0; j < 8; j++)
                    acc[i][j] = fmaf(ar[i], br[j], acc[i][j]);
        }
        __syncthreads();
    }
#pragma unroll
    for (int i = 0; i < 8; i++) {
        size_t off = (size_t)(bm + ty * 8 + i) * N + bn + tx * 8;
        float* cp = C + off;
        const float* ap = addend + off;
#pragma unroll
        for (int j = 0; j < 8; j++) cp[j] = acc[i][j] + ap[j];
    }
}

// ---------------- column softmax stats (over L) — deterministic two-level -------
__global__ __launch_bounds__(256) void smax_pmax_kernel() {
    int cb = blockIdx.x;
    float m[4] = {-3.4e38f, -3.4e38f, -3.4e38f, -3.4e38f};
    for (int r = 0; r < 32; r++) {
        const float* row = g_scores + (size_t)(cb * 32 + r) * Md;
#pragma unroll
        for (int j = 0; j < 4; j++)
            m[j] = fmaxf(m[j], row[threadIdx.x + j * 256]);
    }
#pragma unroll
    for (int j = 0; j < 4; j++)
        g_pmax[(size_t)cb * Md + threadIdx.x + j * 256] = m[j];
}
__global__ __launch_bounds__(256) void smax_cmax_kernel() {
    int c = blockIdx.x * 256 + threadIdx.x;
    float m = -3.4e38f;
    for (int b = 0; b < 128; b++) m = fmaxf(m, g_pmax[(size_t)b * Md + c]);
    g_colmax[c] = m;
}
__global__ __launch_bounds__(256) void smax_psum_kernel() {
    int cb = blockIdx.x;
    float cm[4], s[4] = {0.f, 0.f, 0.f, 0.f};
#pragma unroll
    for (int j = 0; j < 4; j++) cm[j] = g_colmax[threadIdx.x + j * 256];
    for (int r = 0; r < 32; r++) {
        const float* row = g_scores + (size_t)(cb * 32 + r) * Md;
#pragma unroll
        for (int j = 0; j < 4; j++)
            s[j] += __expf(row[threadIdx.x + j * 256] - cm[j]);
    }
#pragma unroll
    for (int j = 0; j < 4; j++)
        g_psum[(size_t)cb * Md + threadIdx.x + j * 256] = s[j];
}
__global__ __launch_bounds__(256) void smax_csum_kernel() {
    int c = blockIdx.x * 256 + threadIdx.x;
    float s = 0.f;
    for (int b = 0; b < 128; b++) s += g_psum[(size_t)b * Md + c];
    g_colsumr[c] = 1.0f / s;
}

// ---------------- A -> A_new[0:1024] copy ---------------------------------------
__global__ __launch_bounds__(256) void copyA_kernel(const float* __restrict__ A,
                                                    float* __restrict__ dst) {
    size_t i = (size_t)blockIdx.x * blockDim.x + threadIdx.x;   // float4 index
    ((float4*)dst)[i] = ((const float4*)A)[i];
}

// ---------------- persistent LSTM scan ------------------------------------------
// 128 CTAs x 256 threads. CTA b owns h indices [4b, 4b+4) -> 16 gate rows.
// Warp w computes gate rows 2w, 2w+1. Lane l owns h-slice [16l, 16l+16).
// Exchange: self-validating {value, step-tag} u64 words with RELAXED strong
// accesses — atomic pairing provides correctness; no release ordering means the
// publish never waits on the previous step's DRAM-bound out_seq store.
__global__ __launch_bounds__(256, 1) void lstm_kernel(
    const float* __restrict__ Whh, const float* __restrict__ h0,
    const float* __restrict__ c0, float* __restrict__ out_h,
    float* __restrict__ out_c, float* __restrict__ out_seq,
    float* __restrict__ out_anew_last)
{
    __shared__ float hs[Hd];
    __shared__ float gs[16];
    int bid = blockIdx.x, tid = threadIdx.x;
    int w = tid >> 5, l = tid & 31;
    int rl0 = 2 * w, rl1 = 2 * w + 1;
    // global gate row: gate g = r>>2 (i,f,g,o blocks of 512), within-gate idx bid*4+(r&3)
    int grow0 = (rl0 >> 2) * Hd + bid * 4 + (rl0 & 3);
    int grow1 = (rl1 >> 2) * Hd + bid * 4 + (rl1 & 3);   // == grow0 + 1

    float wr0[16], wr1[16];
    {
        const float4* p0 = (const float4*)(Whh + (size_t)grow0 * Hd + l * 16);
        const float4* p1 = (const float4*)(Whh + (size_t)grow1 * Hd + l * 16);
#pragma unroll
        for (int m = 0; m < 4; m++) {
            float4 v0 = p0[m], v1 = p1[m];
            wr0[4 * m + 0] = v0.x; wr0[4 * m + 1] = v0.y;
            wr0[4 * m + 2] = v0.z; wr0[4 * m + 3] = v0.w;
            wr1[4 * m + 0] = v1.x; wr1[4 * m + 1] = v1.y;
            wr1[4 * m + 2] = v1.z; wr1[4 * m + 3] = v1.w;
        }
    }
    hs[tid] = h0[tid];
    hs[tid + 256] = h0[tid + 256];
    float creg = (tid < 4) ? c0[bid * 4 + tid] : 0.f;
    __syncthreads();

    for (int t = 0; t < Ld; t++) {
        // overlap: lane0 of each warp prefetches the two pre-activations (adjacent)
        float2 pre2 = make_float2(0.f, 0.f);
        if (l == 0)
            pre2 = __ldcg((const float2*)&g_pre[(size_t)t * G4H + grow0]);

        // dot products over the owned 16-slice (LDS.128, conflict-free)
        float a0 = 0.f, a1 = 0.f;
#pragma unroll
        for (int m = 0; m < 4; m++) {
            float4 h4 = *(const float4*)&hs[l * 16 + 4 * m];
            a0 = fmaf(wr0[4 * m + 0], h4.x, a0); a1 = fmaf(wr1[4 * m + 0], h4.x, a1);
            a0 = fmaf(wr0[4 * m + 1], h4.y, a0); a1 = fmaf(wr1[4 * m + 1], h4.y, a1);
            a0 = fmaf(wr0[4 * m + 2], h4.z, a0); a1 = fmaf(wr1[4 * m + 2], h4.z, a1);
            a0 = fmaf(wr0[4 * m + 3], h4.w, a0); a1 = fmaf(wr1[4 * m + 3], h4.w, a1);
        }
#pragma unroll
        for (int off = 16; off > 0; off >>= 1) {
            a0 += __shfl_down_sync(0xffffffffu, a0, off);
            a1 += __shfl_down_sync(0xffffffffu, a1, off);
        }
        if (l == 0) { gs[rl0] = a0 + pre2.x; gs[rl1] = a1 + pre2.y; }
        __syncthreads();

        int nb = (t + 1) & 1;
        unsigned tgt = (unsigned)(t + 1);

        if (tid < 4) {
            float iv = sigf(gs[tid]);
            float fv = sigf(gs[4 + tid]);
            float gv = tanh_acc(gs[8 + tid]);
            float ov = sigf(gs[12 + tid]);
            float cv = fmaf(fv, creg, iv * gv);
            creg = cv;
            float hv = ov * tanh_acc(cv);
            int hidx = bid * 4 + tid;
            unsigned long long pkt =
                ((unsigned long long)tgt << 32) | (unsigned long long)__float_as_uint(hv);
            st_rlx_u64(&g_hpair[nb][hidx], pkt);          // relaxed strong publish
            __stcg(&out_seq[(size_t)t * Hd + hidx], hv);
            if (t == Ld - 1) {
                out_h[hidx] = hv;
                out_c[hidx] = cv;
                out_anew_last[hidx] = hv;
            }
        }
        if (t == Ld - 1) break;

        // poll BOTH tagged words concurrently each iteration (relaxed strong)
        {
            const unsigned long long* p0 = &g_hpair[nb][tid];
            const unsigned long long* p1 = &g_hpair[nb][tid + 256];
            unsigned long long v0 = ld_rlx_u64(p0);
            unsigned long long v1 = ld_rlx_u64(p1);
            bool ok0 = (unsigned)(v0 >> 32) >= tgt;
            bool ok1 = (unsigned)(v1 >> 32) >= tgt;
            while (!(ok0 && ok1)) {
                if (!ok0) { v0 = ld_rlx_u64(p0); ok0 = (unsigned)(v0 >> 32) >= tgt; }
                if (!ok1) { v1 = ld_rlx_u64(p1); ok1 = (unsigned)(v1 >> 32) >= tgt; }
            }
            hs[tid]       = __uint_as_float((unsigned)v0);
            hs[tid + 256] = __uint_as_float((unsigned)v1);
        }
        __syncthreads();
    }
}

// ---------------- launch ---------------------------------------------------------
extern "C" void kernel_launch(void* const* d_in, const int* in_sizes, int n_in,
                              void* d_out, int out_size) {
    const int*   sent  = (const int*)d_in[0];
    const float* h0    = (const float*)d_in[1];
    const float* c0    = (const float*)d_in[2];
    const float* A     = (const float*)d_in[3];
    const float* embed = (const float*)d_in[4];
    const float* W_ih  = (const float*)d_in[5];
    const float* W_hh  = (const float*)d_in[6];
    const float* b_ih  = (const float*)d_in[7];
    const float* b_hh  = (const float*)d_in[8];

    float* out = (float*)d_out;
    float* out_h = out;
    float* out_c = out + Hd;
    float* out_seq = out + 2 * Hd;
    float* out_anew = out + 2 * Hd + (size_t)Ld * Hd;
    float* out_anew_last = out_anew + (size_t)Md * Hd;

    float* d_x0; float* d_scores; float* d_pre;
    cudaGetSymbolAddress((void**)&d_x0, g_x0);
    cudaGetSymbolAddress((void**)&d_scores, g_scores);
    cudaGetSymbolAddress((void**)&d_pre, g_pre);

    init_pairs_kernel<<<4, 256>>>();
    embed_kernel<<<Ld, 128>>>(sent, embed);

    // scores = x0 @ A^T   [4096,1024]
    gemm_nt_kernel<<<dim3(Md / BN, Ld / BM), 256>>>(d_scores, d_x0, A,
                                                    Ld, Md, Hd, nullptr, nullptr);
    // softmax stats over L (columns) — normalization fused into next GEMM
    smax_pmax_kernel<<<128, 256>>>();
    smax_cmax_kernel<<<Md / 256, 256>>>();
    smax_psum_kernel<<<128, 256>>>();
    smax_csum_kernel<<<Md / 256, 256>>>();

    // x = x0 + softmax(scores) @ A    [4096,512] (in place into g_x0)
    gemm_nn_smax_kernel<<<dim3(Hd / BN, Ld / BM), 256>>>(d_x0, d_scores, A,
                                                         Ld, Hd, Md, d_x0);
    // pre = x @ W_ih^T + b_ih + b_hh   [4096,2048]
    gemm_nt_kernel<<<dim3(G4H / BN, Ld / BM), 256>>>(d_pre, d_x0, W_ih,
                                                     Ld, G4H, Hd, b_ih, b_hh);
    // A_new rows 0..1023
    copyA_kernel<<<(Md * Hd / 4) / 256, 256>>>(A, out_anew);

    // LSTM scan (persistent, 128 CTAs)
    lstm_kernel<<<NCTA, 256>>>(W_hh, h0, c0, out_h, out_c, out_seq, out_anew_last);
}

// round 16
// speedup vs baseline: 1.4391x; 1.0775x over previous
#include <cuda_runtime.h>

#define Ld 4096
#define Hd 512
#define Md 1024
#define G4H 2048
#define NCTA 128

// ---------------- scratch (device globals; no allocations allowed) ------------
__device__ float g_x0[Ld * Hd];          // x after embed; later x+att@A in place
__device__ float g_scores[Ld * Md];      // raw scores (softmax fused into gemm_nn)
__device__ float g_pre[Ld * G4H];        // x @ W_ih^T + b_ih + b_hh
__device__ float g_pmax[128 * Md];
__device__ float g_psum[128 * Md];
__device__ float g_colmax[Md];
__device__ float g_colsumr[Md];
__device__ unsigned long long g_hpair[2][Hd];   // {tag(hi32), value bits(lo32)}

// ---------------- helpers ------------------------------------------------------
// RELAXED strong ops: single-copy atomic (all we need for self-validating
// {tag,value} words) WITHOUT release/acquire ordering (R15 win: the release
// publish was waiting on the prior step's DRAM-bound out_seq store).
__device__ __forceinline__ unsigned long long ld_rlx_u64(const unsigned long long* p) {
    unsigned long long v;
    asm volatile("ld.relaxed.gpu.global.b64 %0, [%1];" : "=l"(v) : "l"(p) : "memory");
    return v;
}
__device__ __forceinline__ void st_rlx_u64(unsigned long long* p, unsigned long long v) {
    asm volatile("st.relaxed.gpu.global.b64 [%0], %1;" :: "l"(p), "l"(v) : "memory");
}
__device__ __forceinline__ float sigf(float x) { return 1.0f / (1.0f + __expf(-x)); }
// exact-identity tanh via __expf (same error class as sigf; avoids branchy tanhf)
__device__ __forceinline__ float tanh_acc(float x) {
    return fmaf(2.0f, 1.0f / (1.0f + __expf(-2.0f * x)), -1.0f);
}

// ---------------- init ---------------------------------------------------------
__global__ void init_pairs_kernel() {
    int i = blockIdx.x * blockDim.x + threadIdx.x;   // 2*Hd entries
    if (i < 2 * Hd) ((unsigned long long*)g_hpair)[i] = 0ull;
}

// ---------------- embedding gather ---------------------------------------------
__global__ __launch_bounds__(128) void embed_kernel(const int* __restrict__ sent,
                                                    const float* __restrict__ embed) {
    int l = blockIdx.x;
    int idx = sent[l];
    const float4* src = (const float4*)(embed + (size_t)idx * Hd);
    float4* dst = (float4*)(g_x0 + (size_t)l * Hd);
    dst[threadIdx.x] = src[threadIdx.x];
}

// ---------------- tiled SGEMM (NT): C[M,N] = A[M,K] * B[N,K]^T (+bias1+bias2) ---
#define BM 128
#define BN 128
#define BK 16
__global__ __launch_bounds__(256) void gemm_nt_kernel(
    float* __restrict__ C, const float* __restrict__ A, const float* __restrict__ B,
    int M, int N, int K, const float* __restrict__ bias1, const float* __restrict__ bias2)
{
    __shared__ float As[BK][BM + 4];
    __shared__ float Bs[BK][BN + 4];
    int tid = threadIdx.x;
    int bm = blockIdx.y * BM, bn = blockIdx.x * BN;
    int tx = tid & 15, ty = tid >> 4;
    float acc[8][8] = {};
    for (int kk = 0; kk < K; kk += BK) {
#pragma unroll
        for (int i = 0; i < 2; i++) {
            int idx = tid + i * 256;
            int row = idx >> 2, kc = (idx & 3) << 2;
            float4 v = *(const float4*)(A + (size_t)(bm + row) * K + kk + kc);
            As[kc + 0][row] = v.x; As[kc + 1][row] = v.y;
            As[kc + 2][row] = v.z; As[kc + 3][row] = v.w;
        }
#pragma unroll
        for (int i = 0; i < 2; i++) {
            int idx = tid + i * 256;
            int row = idx >> 2, kc = (idx & 3) << 2;
            float4 v = *(const float4*)(B + (size_t)(bn + row) * K + kk + kc);
            Bs[kc + 0][row] = v.x; Bs[kc + 1][row] = v.y;
            Bs[kc + 2][row] = v.z; Bs[kc + 3][row] = v.w;
        }
        __syncthreads();
#pragma unroll
        for (int k = 0; k < BK; k++) {
            float ar[8], br[8];
            *(float4*)(ar)     = *(const float4*)&As[k][ty * 8];
            *(float4*)(ar + 4) = *(const float4*)&As[k][ty * 8 + 4];
            *(float4*)(br)     = *(const float4*)&Bs[k][tx * 8];
            *(float4*)(br + 4) = *(const float4*)&Bs[k][tx * 8 + 4];
#pragma unroll
            for (int i = 0; i < 8; i++)
#pragma unroll
                for (int j = 0; j < 8; j++)
                    acc[i][j] = fmaf(ar[i], br[j], acc[i][j]);
        }
        __syncthreads();
    }
    float bb[8];
#pragma unroll
    for (int j = 0; j < 8; j++) {
        float b = 0.f;
        if (bias1) b += bias1[bn + tx * 8 + j];
        if (bias2) b += bias2[bn + tx * 8 + j];
        bb[j] = b;
    }
#pragma unroll
    for (int i = 0; i < 8; i++) {
        float* cp = C + (size_t)(bm + ty * 8 + i) * N + bn + tx * 8;
#pragma unroll
        for (int j = 0; j < 8; j++) cp[j] = acc[i][j] + bb[j];
    }
}

// ---------------- tiled SGEMM (NN) with fused softmax on A ----------------------
__global__ __launch_bounds__(256) void gemm_nn_smax_kernel(
    float* __restrict__ C, const float* __restrict__ A, const float* __restrict__ B,
    int M, int N, int K, const float* __restrict__ addend)
{
    __shared__ float As[BK][BM + 4];
    __shared__ float Bs[BK][BN + 4];
    int tid = threadIdx.x;
    int bm = blockIdx.y * BM, bn = blockIdx.x * BN;
    int tx = tid & 15, ty = tid >> 4;
    float acc[8][8] = {};
    for (int kk = 0; kk < K; kk += BK) {
#pragma unroll
        for (int i = 0; i < 2; i++) {
            int idx = tid + i * 256;
            int row = idx >> 2, kc = (idx & 3) << 2;
            float4 v = *(const float4*)(A + (size_t)(bm + row) * K + kk + kc);
            float4 cm = *(const float4*)&g_colmax[kk + kc];
            float4 cr = *(const float4*)&g_colsumr[kk + kc];
            As[kc + 0][row] = __expf(v.x - cm.x) * cr.x;
            As[kc + 1][row] = __expf(v.y - cm.y) * cr.y;
            As[kc + 2][row] = __expf(v.z - cm.z) * cr.z;
            As[kc + 3][row] = __expf(v.w - cm.w) * cr.w;
        }
#pragma unroll
        for (int i = 0; i < 2; i++) {
            int idx = tid + i * 256;
            int kr = idx >> 5, col = (idx & 31) << 2;
            float4 v = *(const float4*)(B + (size_t)(kk + kr) * N + bn + col);
            *(float4*)&Bs[kr][col] = v;
        }
        __syncthreads();
#pragma unroll
        for (int k = 0; k < BK; k++) {
            float ar[8], br[8];
            *(float4*)(ar)     = *(const float4*)&As[k][ty * 8];
            *(float4*)(ar + 4) = *(const float4*)&As[k][ty * 8 + 4];
            *(float4*)(br)     = *(const float4*)&Bs[k][tx * 8];
            *(float4*)(br + 4) = *(const float4*)&Bs[k][tx * 8 + 4];
#pragma unroll
            for (int i = 0; i < 8; i++)
#pragma unroll
                for (int j = 0; j < 8; j++)
                    acc[i][j] = fmaf(ar[i], br[j], acc[i][j]);
        }
        __syncthreads();
    }
#pragma unroll
    for (int i = 0; i < 8; i++) {
        size_t off = (size_t)(bm + ty * 8 + i) * N + bn + tx * 8;
        float* cp = C + off;
        const float* ap = addend + off;
#pragma unroll
        for (int j = 0; j < 8; j++) cp[j] = acc[i][j] + ap[j];
    }
}

// ---------------- column softmax stats (over L) — deterministic two-level -------
__global__ __launch_bounds__(256) void smax_pmax_kernel() {
    int cb = blockIdx.x;
    float m[4] = {-3.4e38f, -3.4e38f, -3.4e38f, -3.4e38f};
    for (int r = 0; r < 32; r++) {
        const float* row = g_scores + (size_t)(cb * 32 + r) * Md;
#pragma unroll
        for (int j = 0; j < 4; j++)
            m[j] = fmaxf(m[j], row[threadIdx.x + j * 256]);
    }
#pragma unroll
    for (int j = 0; j < 4; j++)
        g_pmax[(size_t)cb * Md + threadIdx.x + j * 256] = m[j];
}
__global__ __launch_bounds__(256) void smax_cmax_kernel() {
    int c = blockIdx.x * 256 + threadIdx.x;
    float m = -3.4e38f;
    for (int b = 0; b < 128; b++) m = fmaxf(m, g_pmax[(size_t)b * Md + c]);
    g_colmax[c] = m;
}
__global__ __launch_bounds__(256) void smax_psum_kernel() {
    int cb = blockIdx.x;
    float cm[4], s[4] = {0.f, 0.f, 0.f, 0.f};
#pragma unroll
    for (int j = 0; j < 4; j++) cm[j] = g_colmax[threadIdx.x + j * 256];
    for (int r = 0; r < 32; r++) {
        const float* row = g_scores + (size_t)(cb * 32 + r) * Md;
#pragma unroll
        for (int j = 0; j < 4; j++)
            s[j] += __expf(row[threadIdx.x + j * 256] - cm[j]);
    }
#pragma unroll
    for (int j = 0; j < 4; j++)
        g_psum[(size_t)cb * Md + threadIdx.x + j * 256] = s[j];
}
__global__ __launch_bounds__(256) void smax_csum_kernel() {
    int c = blockIdx.x * 256 + threadIdx.x;
    float s = 0.f;
    for (int b = 0; b < 128; b++) s += g_psum[(size_t)b * Md + c];
    g_colsumr[c] = 1.0f / s;
}

// ---------------- A -> A_new[0:1024] copy ---------------------------------------
__global__ __launch_bounds__(256) void copyA_kernel(const float* __restrict__ A,
                                                    float* __restrict__ dst) {
    size_t i = (size_t)blockIdx.x * blockDim.x + threadIdx.x;   // float4 index
    ((float4*)dst)[i] = ((const float4*)A)[i];
}

// ---------------- persistent LSTM scan ------------------------------------------
// 128 CTAs x 256 threads. CTA b owns h indices [4b, 4b+4) -> 16 gate rows.
// Warp w computes gate rows 2w, 2w+1. Lane l owns h-slice [16l, 16l+16).
// Exchange: self-validating {value, step-tag} u64 words with RELAXED strong
// accesses (R15 champion). NEW: g_pre load software-pipelined one step ahead —
// issued in the poll-wait window, consumed from registers at the gs write, so
// the publisher's serial chain has no long-scoreboard memory dependency.
__global__ __launch_bounds__(256, 1) void lstm_kernel(
    const float* __restrict__ Whh, const float* __restrict__ h0,
    const float* __restrict__ c0, float* __restrict__ out_h,
    float* __restrict__ out_c, float* __restrict__ out_seq,
    float* __restrict__ out_anew_last)
{
    __shared__ float hs[Hd];
    __shared__ float gs[16];
    int bid = blockIdx.x, tid = threadIdx.x;
    int w = tid >> 5, l = tid & 31;
    int rl0 = 2 * w, rl1 = 2 * w + 1;
    // global gate row: gate g = r>>2 (i,f,g,o blocks of 512), within-gate idx bid*4+(r&3)
    int grow0 = (rl0 >> 2) * Hd + bid * 4 + (rl0 & 3);
    int grow1 = (rl1 >> 2) * Hd + bid * 4 + (rl1 & 3);   // == grow0 + 1

    float wr0[16], wr1[16];
    {
        const float4* p0 = (const float4*)(Whh + (size_t)grow0 * Hd + l * 16);
        const float4* p1 = (const float4*)(Whh + (size_t)grow1 * Hd + l * 16);
#pragma unroll
        for (int m = 0; m < 4; m++) {
            float4 v0 = p0[m], v1 = p1[m];
            wr0[4 * m + 0] = v0.x; wr0[4 * m + 1] = v0.y;
            wr0[4 * m + 2] = v0.z; wr0[4 * m + 3] = v0.w;
            wr1[4 * m + 0] = v1.x; wr1[4 * m + 1] = v1.y;
            wr1[4 * m + 2] = v1.z; wr1[4 * m + 3] = v1.w;
        }
    }
    hs[tid] = h0[tid];
    hs[tid + 256] = h0[tid + 256];
    float creg = (tid < 4) ? c0[bid * 4 + tid] : 0.f;

    // pre-activation pipeline register: load step 0's values before the loop
    float2 pre_cur = make_float2(0.f, 0.f);
    if (l == 0)
        pre_cur = __ldcg((const float2*)&g_pre[grow0]);
    __syncthreads();

    for (int t = 0; t < Ld; t++) {
        // dot products over the owned 16-slice (LDS.128, conflict-free)
        float a0 = 0.f, a1 = 0.f;
#pragma unroll
        for (int m = 0; m < 4; m++) {
            float4 h4 = *(const float4*)&hs[l * 16 + 4 * m];
            a0 = fmaf(wr0[4 * m + 0], h4.x, a0); a1 = fmaf(wr1[4 * m + 0], h4.x, a1);
            a0 = fmaf(wr0[4 * m + 1], h4.y, a0); a1 = fmaf(wr1[4 * m + 1], h4.y, a1);
            a0 = fmaf(wr0[4 * m + 2], h4.z, a0); a1 = fmaf(wr1[4 * m + 2], h4.z, a1);
            a0 = fmaf(wr0[4 * m + 3], h4.w, a0); a1 = fmaf(wr1[4 * m + 3], h4.w, a1);
        }
#pragma unroll
        for (int off = 16; off > 0; off >>= 1) {
            a0 += __shfl_down_sync(0xffffffffu, a0, off);
            a1 += __shfl_down_sync(0xffffffffu, a1, off);
        }
        if (l == 0) { gs[rl0] = a0 + pre_cur.x; gs[rl1] = a1 + pre_cur.y; }
        __syncthreads();

        int nb = (t + 1) & 1;
        unsigned tgt = (unsigned)(t + 1);

        if (tid < 4) {
            float iv = sigf(gs[tid]);
            float fv = sigf(gs[4 + tid]);
            float gv = tanh_acc(gs[8 + tid]);
            float ov = sigf(gs[12 + tid]);
            float cv = fmaf(fv, creg, iv * gv);
            creg = cv;
            float hv = ov * tanh_acc(cv);
            int hidx = bid * 4 + tid;
            unsigned long long pkt =
                ((unsigned long long)tgt << 32) | (unsigned long long)__float_as_uint(hv);
            st_rlx_u64(&g_hpair[nb][hidx], pkt);          // relaxed strong publish
            __stcg(&out_seq[(size_t)t * Hd + hidx], hv);
            if (t == Ld - 1) {
                out_h[hidx] = hv;
                out_c[hidx] = cv;
                out_anew_last[hidx] = hv;
            }
        }
        if (t == Ld - 1) break;

        // prefetch next step's pre-activations in the wait window (lane0/warp)
        if (l == 0)
            pre_cur = __ldcg((const float2*)&g_pre[(size_t)(t + 1) * G4H + grow0]);

        // poll BOTH tagged words concurrently each iteration (relaxed strong)
        {
            const unsigned long long* p0 = &g_hpair[nb][tid];
            const unsigned long long* p1 = &g_hpair[nb][tid + 256];
            unsigned long long v0 = ld_rlx_u64(p0);
            unsigned long long v1 = ld_rlx_u64(p1);
            bool ok0 = (unsigned)(v0 >> 32) >= tgt;
            bool ok1 = (unsigned)(v1 >> 32) >= tgt;
            while (!(ok0 && ok1)) {
                if (!ok0) { v0 = ld_rlx_u64(p0); ok0 = (unsigned)(v0 >> 32) >= tgt; }
                if (!ok1) { v1 = ld_rlx_u64(p1); ok1 = (unsigned)(v1 >> 32) >= tgt; }
            }
            hs[tid]       = __uint_as_float((unsigned)v0);
            hs[tid + 256] = __uint_as_float((unsigned)v1);
        }
        __syncthreads();
    }
}

// ---------------- launch ---------------------------------------------------------
extern "C" void kernel_launch(void* const* d_in, const int* in_sizes, int n_in,
                              void* d_out, int out_size) {
    const int*   sent  = (const int*)d_in[0];
    const float* h0    = (const float*)d_in[1];
    const float* c0    = (const float*)d_in[2];
    const float* A     = (const float*)d_in[3];
    const float* embed = (const float*)d_in[4];
    const float* W_ih  = (const float*)d_in[5];
    const float* W_hh  = (const float*)d_in[6];
    const float* b_ih  = (const float*)d_in[7];
    const float* b_hh  = (const float*)d_in[8];

    float* out = (float*)d_out;
    float* out_h = out;
    float* out_c = out + Hd;
    float* out_seq = out + 2 * Hd;
    float* out_anew = out + 2 * Hd + (size_t)Ld * Hd;
    float* out_anew_last = out_anew + (size_t)Md * Hd;

    float* d_x0; float* d_scores; float* d_pre;
    cudaGetSymbolAddress((void**)&d_x0, g_x0);
    cudaGetSymbolAddress((void**)&d_scores, g_scores);
    cudaGetSymbolAddress((void**)&d_pre, g_pre);

    init_pairs_kernel<<<4, 256>>>();
    embed_kernel<<<Ld, 128>>>(sent, embed);

    // scores = x0 @ A^T   [4096,1024]
    gemm_nt_kernel<<<dim3(Md / BN, Ld / BM), 256>>>(d_scores, d_x0, A,
                                                    Ld, Md, Hd, nullptr, nullptr);
    // softmax stats over L (columns) — normalization fused into next GEMM
    smax_pmax_kernel<<<128, 256>>>();
    smax_cmax_kernel<<<Md / 256, 256>>>();
    smax_psum_kernel<<<128, 256>>>();
    smax_csum_kernel<<<Md / 256, 256>>>();

    // x = x0 + softmax(scores) @ A    [4096,512] (in place into g_x0)
    gemm_nn_smax_kernel<<<dim3(Hd / BN, Ld / BM), 256>>>(d_x0, d_scores, A,
                                                         Ld, Hd, Md, d_x0);
    // pre = x @ W_ih^T + b_ih + b_hh   [4096,2048]
    gemm_nt_kernel<<<dim3(G4H / BN, Ld / BM), 256>>>(d_pre, d_x0, W_ih,
                                                     Ld, G4H, Hd, b_ih, b_hh);
    // A_new rows 0..1023
    copyA_kernel<<<(Md * Hd / 4) / 256, 256>>>(A, out_anew);

    // LSTM scan (persistent, 128 CTAs)
    lstm_kernel<<<NCTA, 256>>>(W_hh, h0, c0, out_h, out_c, out_seq, out_anew_last);
}